// round 5
// baseline (speedup 1.0000x reference)
#include <cuda_runtime.h>
#include <math.h>

#define DM      128
#define HID     256
#define NN      17
#define ND      32
#define NODEF   (NN*ND)      // 544
#define M_MAX   65536

// Scratch (no cudaMalloc allowed) -------------------------------------------
__device__ float g_h[M_MAX * HID];         // [M,256] hidden after GELU
__device__ float g_nodes[M_MAX * NODEF];   // [M,544] node features
__device__ float g_adjS1[NN * NN];
__device__ float g_adjS2[NN * NN];

__device__ __forceinline__ float gelu_erf(float x) {
    // exact (erf) GELU, matching jax.nn.gelu(approximate=False)
    return 0.5f * x * (1.0f + erff(x * 0.70710678118654752440f));
}

// ---------------------------------------------------------------------------
// adj softmax precompute: rows 0..16 -> adj1, 17..33 -> adj2
// ---------------------------------------------------------------------------
__global__ void adj_softmax_kernel(const float* __restrict__ a1,
                                   const float* __restrict__ a2) {
    int t = threadIdx.x;
    const float* src;
    float* dst;
    int r;
    if (t < NN)           { src = a1; dst = g_adjS1; r = t; }
    else if (t < 2 * NN)  { src = a2; dst = g_adjS2; r = t - NN; }
    else return;

    const float* row = src + r * NN;
    float m = -3.0e38f;
    #pragma unroll
    for (int j = 0; j < NN; j++) m = fmaxf(m, row[j]);
    float e[NN];
    float s = 0.0f;
    #pragma unroll
    for (int j = 0; j < NN; j++) { e[j] = expf(row[j] - m); s += e[j]; }
    float inv = 1.0f / s;
    #pragma unroll
    for (int j = 0; j < NN; j++) dst[r * NN + j] = e[j] * inv;
}

// ---------------------------------------------------------------------------
// Register-tiled SGEMM: C[M,N] = op(A[M,K] @ B[K,N] + bias[N])
// BM=128, BN=128, BK=8, 256 threads, 8x8 per-thread microtile.
// ---------------------------------------------------------------------------
template <bool DO_GELU>
__global__ __launch_bounds__(256)
void sgemm_bias_kernel(const float* __restrict__ A,
                       const float* __restrict__ B,
                       const float* __restrict__ bias,
                       float* __restrict__ C,
                       int M, int N, int K) {
    constexpr int BM = 128, BN = 128, BK = 8, TM = 8, TN = 8;
    __shared__ float As[BK][BM];
    __shared__ float Bs[BK][BN];

    const int tid = threadIdx.x;
    const int bm = blockIdx.y * BM;
    const int bn = blockIdx.x * BN;

    const int tx = tid & 15;
    const int ty = tid >> 4;

    const int aRow = tid >> 1;
    const int aCol = (tid & 1) * 4;
    const int bRow = tid >> 5;
    const int bCol = (tid & 31) * 4;

    float acc[TM][TN];
    #pragma unroll
    for (int i = 0; i < TM; i++)
        #pragma unroll
        for (int j = 0; j < TN; j++) acc[i][j] = 0.0f;

    for (int k0 = 0; k0 < K; k0 += BK) {
        float4 av = *reinterpret_cast<const float4*>(
            &A[(size_t)(bm + aRow) * K + k0 + aCol]);
        As[aCol + 0][aRow] = av.x;
        As[aCol + 1][aRow] = av.y;
        As[aCol + 2][aRow] = av.z;
        As[aCol + 3][aRow] = av.w;

        float4 bv = make_float4(0.f, 0.f, 0.f, 0.f);
        if (bn + bCol < N)
            bv = *reinterpret_cast<const float4*>(
                &B[(size_t)(k0 + bRow) * N + bn + bCol]);
        *reinterpret_cast<float4*>(&Bs[bRow][bCol]) = bv;

        __syncthreads();

        #pragma unroll
        for (int kk = 0; kk < BK; kk++) {
            float a[TM], b[TN];
            float4 a0 = *reinterpret_cast<const float4*>(&As[kk][ty * TM]);
            float4 a1 = *reinterpret_cast<const float4*>(&As[kk][ty * TM + 4]);
            a[0] = a0.x; a[1] = a0.y; a[2] = a0.z; a[3] = a0.w;
            a[4] = a1.x; a[5] = a1.y; a[6] = a1.z; a[7] = a1.w;
            float4 b0 = *reinterpret_cast<const float4*>(&Bs[kk][tx * TN]);
            float4 b1 = *reinterpret_cast<const float4*>(&Bs[kk][tx * TN + 4]);
            b[0] = b0.x; b[1] = b0.y; b[2] = b0.z; b[3] = b0.w;
            b[4] = b1.x; b[5] = b1.y; b[6] = b1.z; b[7] = b1.w;
            #pragma unroll
            for (int i = 0; i < TM; i++)
                #pragma unroll
                for (int j = 0; j < TN; j++)
                    acc[i][j] = fmaf(a[i], b[j], acc[i][j]);
        }
        __syncthreads();
    }

    #pragma unroll
    for (int i = 0; i < TM; i++) {
        const int row = bm + ty * TM + i;
        #pragma unroll
        for (int j = 0; j < TN; j++) {
            const int col = bn + tx * TN + j;
            if (col < N) {
                float v = acc[i][j] + bias[col];
                if (DO_GELU) v = gelu_erf(v);
                C[(size_t)row * N + col] = v;
            }
        }
    }
}

// ---------------------------------------------------------------------------
// Fused GAT1 -> GAT2 -> coord projection, v2 (MIO-minimized).
// 544 threads = 17 warps; warp i owns joint i, lane f owns feature f.
//  - A rows in registers (warp-uniform)
//  - W columns in registers (per-lane)
//  - lin stage reads warp-private sMix via broadcast float4 LDS (1 cyc/op)
//  - double-buffered sN: only 2 __syncthreads per token
//  - next-token node value prefetched under compute
// ---------------------------------------------------------------------------
__global__ __launch_bounds__(544, 1)
void gat_fused_kernel(const float* __restrict__ nodes_in,
                      const float* __restrict__ Wg1, const float* __restrict__ bg1,
                      const float* __restrict__ Wg2, const float* __restrict__ bg2,
                      const float* __restrict__ Wc,  const float* __restrict__ bc,
                      float* __restrict__ out,
                      int ntok, int tok_per_block) {
    __shared__ float sN0[NN][ND];
    __shared__ float sN1[NN][ND];
    __shared__ float sMix[NN][ND];     // warp-private rows (row i used by warp i)

    const int tid = threadIdx.x;
    const int i = tid >> 5;   // joint  (warp id, 0..16) — warp-uniform
    const int f = tid & 31;   // feature (lane)

    // ---- one-time weight staging into registers ----
    float a1[NN], a2[NN];              // adjacency rows (warp-uniform)
    #pragma unroll
    for (int j = 0; j < NN; j++) {
        a1[j] = g_adjS1[i * NN + j];
        a2[j] = g_adjS2[i * NN + j];
    }
    float w1[ND], w2[ND];              // weight columns for this lane's feature
    #pragma unroll
    for (int k = 0; k < ND; k++) {
        w1[k] = Wg1[k * ND + f];
        w2[k] = Wg2[k * ND + f];
    }
    const float bias1 = bg1[f];
    const float bias2 = bg2[f];
    const float wc0 = Wc[f * 2 + 0];
    const float wc1 = Wc[f * 2 + 1];
    const float c0 = bc[0], c1 = bc[1];

    const int t0 = blockIdx.x * tok_per_block;
    const int t1 = min(t0 + tok_per_block, ntok);
    if (t0 >= t1) return;

    float ncur = nodes_in[(size_t)t0 * NODEF + i * ND + f];

    for (int t = t0; t < t1; t++) {
        sN0[i][f] = ncur;
        __syncthreads();                          // bar 1: sN0 ready

        // prefetch next token's node value (hidden under this token's compute)
        float nnext = 0.0f;
        if (t + 1 < t1)
            nnext = nodes_in[(size_t)(t + 1) * NODEF + i * ND + f];

        // ---------- GAT layer 1 ----------
        // graph mix: mix[i][f] = sum_j A1[i][j] * n[j][f]
        float m0 = 0.0f, m1 = 0.0f;
        #pragma unroll
        for (int j = 0; j < NN - 1; j += 2) {
            m0 = fmaf(a1[j],     sN0[j][f],     m0);
            m1 = fmaf(a1[j + 1], sN0[j + 1][f], m1);
        }
        m0 = fmaf(a1[NN - 1], sN0[NN - 1][f], m0);
        const float mixv1 = m0 + m1;

        sMix[i][f] = mixv1;                       // warp-private row
        __syncwarp();
        // linear: lin[f] = b1[f] + sum_k mix[i][k] * W1[k][f]
        float l0 = bias1, l1 = 0.0f;
        {
            const float4* rp = reinterpret_cast<const float4*>(&sMix[i][0]);
            #pragma unroll
            for (int c = 0; c < ND / 4; c++) {    // broadcast float4 reads
                float4 q = rp[c];
                l0 = fmaf(q.x, w1[c * 4 + 0], l0);
                l1 = fmaf(q.y, w1[c * 4 + 1], l1);
                l0 = fmaf(q.z, w1[c * 4 + 2], l0);
                l1 = fmaf(q.w, w1[c * 4 + 3], l1);
            }
        }
        const float v1 = gelu_erf(l0 + l1) + ncur;

        sN1[i][f] = v1;
        __syncthreads();                          // bar 2: sN1 ready

        // ---------- GAT layer 2 ----------
        m0 = 0.0f; m1 = 0.0f;
        #pragma unroll
        for (int j = 0; j < NN - 1; j += 2) {
            m0 = fmaf(a2[j],     sN1[j][f],     m0);
            m1 = fmaf(a2[j + 1], sN1[j + 1][f], m1);
        }
        m0 = fmaf(a2[NN - 1], sN1[NN - 1][f], m0);
        const float mixv2 = m0 + m1;

        __syncwarp();                             // lanes done reading sMix L1
        sMix[i][f] = mixv2;
        __syncwarp();
        l0 = bias2; l1 = 0.0f;
        {
            const float4* rp = reinterpret_cast<const float4*>(&sMix[i][0]);
            #pragma unroll
            for (int c = 0; c < ND / 4; c++) {
                float4 q = rp[c];
                l0 = fmaf(q.x, w2[c * 4 + 0], l0);
                l1 = fmaf(q.y, w2[c * 4 + 1], l1);
                l0 = fmaf(q.z, w2[c * 4 + 2], l0);
                l1 = fmaf(q.w, w2[c * 4 + 3], l1);
            }
        }
        const float v2 = gelu_erf(l0 + l1) + v1;
        __syncwarp();                             // before next token's sMix write

        // ---------- coord projection (per-warp butterfly reduce) ----------
        float p0 = v2 * wc0;
        float p1 = v2 * wc1;
        #pragma unroll
        for (int off = 16; off > 0; off >>= 1) {
            p0 += __shfl_xor_sync(0xffffffffu, p0, off);
            p1 += __shfl_xor_sync(0xffffffffu, p1, off);
        }
        if (f == 0) {
            float2 r = make_float2(p0 + c0, p1 + c1);
            reinterpret_cast<float2*>(out)[(size_t)t * NN + i] = r;
        }

        ncur = nnext;
        // NOTE: next iteration's write to sN0 is safe: every warp's reads of
        // sN0(t) happened before its own arrival at bar 2 above.
    }
}

// ---------------------------------------------------------------------------
extern "C" void kernel_launch(void* const* d_in, const int* in_sizes, int n_in,
                              void* d_out, int out_size) {
    const float* x    = (const float*)d_in[0];
    const float* W1   = (const float*)d_in[1];
    const float* b1   = (const float*)d_in[2];
    const float* W2   = (const float*)d_in[3];
    const float* b2   = (const float*)d_in[4];
    const float* adj1 = (const float*)d_in[5];
    const float* Wg1  = (const float*)d_in[6];
    const float* bg1  = (const float*)d_in[7];
    const float* adj2 = (const float*)d_in[8];
    const float* Wg2  = (const float*)d_in[9];
    const float* bg2  = (const float*)d_in[10];
    const float* Wc   = (const float*)d_in[11];
    const float* bc   = (const float*)d_in[12];
    float* out = (float*)d_out;

    const int M = in_sizes[0] / DM;   // 65536 for the reference shapes

    float *hbuf, *nbuf;
    cudaGetSymbolAddress((void**)&hbuf, g_h);
    cudaGetSymbolAddress((void**)&nbuf, g_nodes);

    // 1. adjacency softmax (tiny)
    adj_softmax_kernel<<<1, 64>>>(adj1, adj2);

    // 2. h = gelu(x @ W1 + b1)
    {
        dim3 grid(HID / 128, M / 128);
        sgemm_bias_kernel<true><<<grid, 256>>>(x, W1, b1, hbuf, M, HID, DM);
    }

    // 3. nodes = h @ W2 + b2
    {
        dim3 grid((NODEF + 127) / 128, M / 128);
        sgemm_bias_kernel<false><<<grid, 256>>>(hbuf, W2, b2, nbuf, M, NODEF, HID);
    }

    // 4. fused GAT1 -> GAT2 -> coord head
    {
        const int nblk = 2048;
        const int tpb = (M + nblk - 1) / nblk;
        gat_fused_kernel<<<nblk, 544>>>(nbuf, Wg1, bg1, Wg2, bg2, Wc, bc,
                                        out, M, tpb);
    }
}

// round 7
// speedup vs baseline: 1.5043x; 1.5043x over previous
#include <cuda_runtime.h>
#include <math.h>

#define DM      128
#define HID     256
#define NN      17
#define ND      32
#define NODEF   (NN*ND)      // 544
#define M_MAX   65536

// Scratch (no cudaMalloc allowed) -------------------------------------------
__device__ float g_h[M_MAX * HID];         // [M,256] hidden after GELU
__device__ float g_nodes[M_MAX * NODEF];   // [M,544] node features
__device__ float g_adjS1[NN * NN];
__device__ float g_adjS2[NN * NN];

__device__ __forceinline__ float gelu_erf(float x) {
    return 0.5f * x * (1.0f + erff(x * 0.70710678118654752440f));
}

// ---------------------------------------------------------------------------
// adj softmax precompute: rows 0..16 -> adj1, 17..33 -> adj2
// ---------------------------------------------------------------------------
__global__ void adj_softmax_kernel(const float* __restrict__ a1,
                                   const float* __restrict__ a2) {
    int t = threadIdx.x;
    const float* src;
    float* dst;
    int r;
    if (t < NN)           { src = a1; dst = g_adjS1; r = t; }
    else if (t < 2 * NN)  { src = a2; dst = g_adjS2; r = t - NN; }
    else return;

    const float* row = src + r * NN;
    float m = -3.0e38f;
    #pragma unroll
    for (int j = 0; j < NN; j++) m = fmaxf(m, row[j]);
    float e[NN];
    float s = 0.0f;
    #pragma unroll
    for (int j = 0; j < NN; j++) { e[j] = expf(row[j] - m); s += e[j]; }
    float inv = 1.0f / s;
    #pragma unroll
    for (int j = 0; j < NN; j++) dst[r * NN + j] = e[j] * inv;
}

// ---------------------------------------------------------------------------
// Register-tiled SGEMM (unchanged): C = op(A @ B + bias)
// ---------------------------------------------------------------------------
template <bool DO_GELU>
__global__ __launch_bounds__(256)
void sgemm_bias_kernel(const float* __restrict__ A,
                       const float* __restrict__ B,
                       const float* __restrict__ bias,
                       float* __restrict__ C,
                       int M, int N, int K) {
    constexpr int BM = 128, BN = 128, BK = 8, TM = 8, TN = 8;
    __shared__ float As[BK][BM];
    __shared__ float Bs[BK][BN];

    const int tid = threadIdx.x;
    const int bm = blockIdx.y * BM;
    const int bn = blockIdx.x * BN;

    const int tx = tid & 15;
    const int ty = tid >> 4;

    const int aRow = tid >> 1;
    const int aCol = (tid & 1) * 4;
    const int bRow = tid >> 5;
    const int bCol = (tid & 31) * 4;

    float acc[TM][TN];
    #pragma unroll
    for (int i = 0; i < TM; i++)
        #pragma unroll
        for (int j = 0; j < TN; j++) acc[i][j] = 0.0f;

    for (int k0 = 0; k0 < K; k0 += BK) {
        float4 av = *reinterpret_cast<const float4*>(
            &A[(size_t)(bm + aRow) * K + k0 + aCol]);
        As[aCol + 0][aRow] = av.x;
        As[aCol + 1][aRow] = av.y;
        As[aCol + 2][aRow] = av.z;
        As[aCol + 3][aRow] = av.w;

        float4 bv = make_float4(0.f, 0.f, 0.f, 0.f);
        if (bn + bCol < N)
            bv = *reinterpret_cast<const float4*>(
                &B[(size_t)(k0 + bRow) * N + bn + bCol]);
        *reinterpret_cast<float4*>(&Bs[bRow][bCol]) = bv;

        __syncthreads();

        #pragma unroll
        for (int kk = 0; kk < BK; kk++) {
            float a[TM], b[TN];
            float4 a0 = *reinterpret_cast<const float4*>(&As[kk][ty * TM]);
            float4 a1 = *reinterpret_cast<const float4*>(&As[kk][ty * TM + 4]);
            a[0] = a0.x; a[1] = a0.y; a[2] = a0.z; a[3] = a0.w;
            a[4] = a1.x; a[5] = a1.y; a[6] = a1.z; a[7] = a1.w;
            float4 b0 = *reinterpret_cast<const float4*>(&Bs[kk][tx * TN]);
            float4 b1 = *reinterpret_cast<const float4*>(&Bs[kk][tx * TN + 4]);
            b[0] = b0.x; b[1] = b0.y; b[2] = b0.z; b[3] = b0.w;
            b[4] = b1.x; b[5] = b1.y; b[6] = b1.z; b[7] = b1.w;
            #pragma unroll
            for (int i = 0; i < TM; i++)
                #pragma unroll
                for (int j = 0; j < TN; j++)
                    acc[i][j] = fmaf(a[i], b[j], acc[i][j]);
        }
        __syncthreads();
    }

    #pragma unroll
    for (int i = 0; i < TM; i++) {
        const int row = bm + ty * TM + i;
        #pragma unroll
        for (int j = 0; j < TN; j++) {
            const int col = bn + tx * TN + j;
            if (col < N) {
                float v = acc[i][j] + bias[col];
                if (DO_GELU) v = gelu_erf(v);
                C[(size_t)row * N + col] = v;
            }
        }
    }
}

// ---------------------------------------------------------------------------
// GAT v3: one TOKEN per WARP, barrier-free.
// Lane f holds feature f of all 17 joints in registers.
//  - graph mix: register FMAs, adjacency via broadcast LDS.128
//  - linear: mix -> warp-private smem row, broadcast LDS.128 reads,
//            weight columns in registers
//  - coord: 17 xor-butterflies, lane-selected, one STG.64 per warp
// No __syncthreads in the token loop.
// ---------------------------------------------------------------------------
#define WARPS_PER_BLK 8

// one GAT layer: in[NN] -> out[NN] (out = gelu(mix@W + b) + in)
__device__ __forceinline__ void gat_layer(
    const float (&A)[NN][20],       // padded adjacency (shared)
    float* __restrict__ sMixW,      // this warp's 17x32 scratch (shared)
    const float (&in)[NN], float (&out)[NN],
    const float (&wcol)[ND], float bias, int f)
{
    // ---- graph mix: mix[i][f] = sum_j A[i][j] * in[j] ----
    #pragma unroll
    for (int i = 0; i < NN; i++) {
        const float4* ap = reinterpret_cast<const float4*>(&A[i][0]);
        float ar[20];
        *reinterpret_cast<float4*>(&ar[0])  = ap[0];
        *reinterpret_cast<float4*>(&ar[4])  = ap[1];
        *reinterpret_cast<float4*>(&ar[8])  = ap[2];
        *reinterpret_cast<float4*>(&ar[12]) = ap[3];
        *reinterpret_cast<float4*>(&ar[16]) = ap[4];
        float e0 = 0.f, e1 = 0.f;
        #pragma unroll
        for (int j = 0; j < NN - 1; j += 2) {
            e0 = fmaf(ar[j],     in[j],     e0);
            e1 = fmaf(ar[j + 1], in[j + 1], e1);
        }
        e0 = fmaf(ar[NN - 1], in[NN - 1], e0);
        sMixW[i * ND + f] = e0 + e1;
    }
    __syncwarp();

    // ---- linear + gelu + residual ----
    #pragma unroll
    for (int i = 0; i < NN; i++) {
        const float4* rp = reinterpret_cast<const float4*>(sMixW + i * ND);
        float l0 = bias, l1 = 0.f;
        #pragma unroll
        for (int c = 0; c < ND / 4; c++) {
            float4 q = rp[c];
            l0 = fmaf(q.x, wcol[c * 4 + 0], l0);
            l1 = fmaf(q.y, wcol[c * 4 + 1], l1);
            l0 = fmaf(q.z, wcol[c * 4 + 2], l0);
            l1 = fmaf(q.w, wcol[c * 4 + 3], l1);
        }
        out[i] = gelu_erf(l0 + l1) + in[i];
    }
    __syncwarp();   // lanes done reading sMixW before next layer overwrites it
}

__global__ __launch_bounds__(WARPS_PER_BLK * 32, 2)
void gat_warp_kernel(const float* __restrict__ nodes_in,
                     const float* __restrict__ Wg1, const float* __restrict__ bg1,
                     const float* __restrict__ Wg2, const float* __restrict__ bg2,
                     const float* __restrict__ Wc,  const float* __restrict__ bc,
                     float* __restrict__ out,
                     int ntok) {
    __shared__ float sA1[NN][20];                    // padded adjacency
    __shared__ float sA2[NN][20];
    __shared__ float sMix[WARPS_PER_BLK][NN][ND];    // warp-private scratch

    const int tid = threadIdx.x;
    const int wid = tid >> 5;
    const int f   = tid & 31;

    for (int idx = tid; idx < NN * 20; idx += WARPS_PER_BLK * 32) {
        int r = idx / 20, c = idx % 20;
        sA1[r][c] = (c < NN) ? g_adjS1[r * NN + c] : 0.f;
        sA2[r][c] = (c < NN) ? g_adjS2[r * NN + c] : 0.f;
    }
    __syncthreads();   // once, before the loop

    // loop-invariant per-lane weights
    float wc1[ND], wc2[ND];
    #pragma unroll
    for (int k = 0; k < ND; k++) {
        wc1[k] = Wg1[k * ND + f];
        wc2[k] = Wg2[k * ND + f];
    }
    const float bias1 = bg1[f];
    const float bias2 = bg2[f];
    const float wcA = Wc[f * 2 + 0];
    const float wcB = Wc[f * 2 + 1];
    const float c0 = bc[0], c1 = bc[1];

    float* sMixW = &sMix[wid][0][0];

    const int gwarp  = blockIdx.x * WARPS_PER_BLK + wid;
    const int nwarps = gridDim.x * WARPS_PER_BLK;

    float nA[NN], nB[NN];

    for (int t = gwarp; t < ntok; t += nwarps) {
        const float* tok = nodes_in + (size_t)t * NODEF + f;
        #pragma unroll
        for (int j = 0; j < NN; j++) nA[j] = tok[j * ND];

        gat_layer(sA1, sMixW, nA, nB, wc1, bias1, f);
        gat_layer(sA2, sMixW, nB, nA, wc2, bias2, f);

        // ---- coord projection: 17 xor-butterfly reductions ----
        float o0 = 0.f, o1 = 0.f;
        #pragma unroll
        for (int i = 0; i < NN; i++) {
            float p0 = nA[i] * wcA;
            float p1 = nA[i] * wcB;
            #pragma unroll
            for (int off = 16; off > 0; off >>= 1) {
                p0 += __shfl_xor_sync(0xffffffffu, p0, off);
                p1 += __shfl_xor_sync(0xffffffffu, p1, off);
            }
            if (f == i) { o0 = p0; o1 = p1; }   // lane i keeps joint i's pair
        }
        if (f < NN) {
            float2 r = make_float2(o0 + c0, o1 + c1);
            reinterpret_cast<float2*>(out + (size_t)t * (NN * 2))[f] = r;
        }
    }
}

// ---------------------------------------------------------------------------
extern "C" void kernel_launch(void* const* d_in, const int* in_sizes, int n_in,
                              void* d_out, int out_size) {
    const float* x    = (const float*)d_in[0];
    const float* W1   = (const float*)d_in[1];
    const float* b1   = (const float*)d_in[2];
    const float* W2   = (const float*)d_in[3];
    const float* b2   = (const float*)d_in[4];
    const float* adj1 = (const float*)d_in[5];
    const float* Wg1  = (const float*)d_in[6];
    const float* bg1  = (const float*)d_in[7];
    const float* adj2 = (const float*)d_in[8];
    const float* Wg2  = (const float*)d_in[9];
    const float* bg2  = (const float*)d_in[10];
    const float* Wc   = (const float*)d_in[11];
    const float* bc   = (const float*)d_in[12];
    float* out = (float*)d_out;

    const int M = in_sizes[0] / DM;   // 65536 for the reference shapes

    float *hbuf, *nbuf;
    cudaGetSymbolAddress((void**)&hbuf, g_h);
    cudaGetSymbolAddress((void**)&nbuf, g_nodes);

    // 1. adjacency softmax (tiny)
    adj_softmax_kernel<<<1, 64>>>(adj1, adj2);

    // 2. h = gelu(x @ W1 + b1)
    {
        dim3 grid(HID / 128, M / 128);
        sgemm_bias_kernel<true><<<grid, 256>>>(x, W1, b1, hbuf, M, HID, DM);
    }

    // 3. nodes = h @ W2 + b2
    {
        dim3 grid((NODEF + 127) / 128, M / 128);
        sgemm_bias_kernel<false><<<grid, 256>>>(hbuf, W2, b2, nbuf, M, HID == HID ? NODEF : NODEF, HID);
    }

    // 4. fused GAT1 -> GAT2 -> coord head (token-per-warp, barrier-free)
    gat_warp_kernel<<<2048, WARPS_PER_BLK * 32>>>(nbuf, Wg1, bg1, Wg2, bg2,
                                                  Wc, bc, out, M);
}